// round 14
// baseline (speedup 1.0000x reference)
#include <cuda_runtime.h>
#include <cuda_bf16.h>
#include <cstdint>

// Problem constants (from reference)
#define V_SZ     32000
#define D_SZ     5120
#define T_SZ     32
#define B_SZ     4
#define S_SZ     2048
#define VIS_DIM  768
#define N_SHARED (V_SZ + 2)            // 32002
#define NTOK     (B_SZ * S_SZ)         // 8192

// ---------------- K1 gather (TMA ring) — proven 49.7us config ----------
#define THREADS      256
#define ROW_BYTES    (D_SZ * 4)        // 20480 B per row
#define NS           6
#define LOOKAHEAD    4
#define SMEM_BYTES   (128 + NS * ROW_BYTES)   // 123008
#define GRID_GATHER  148
#define TOK_PER_BLK  56

// ---------------- K2 vision (list-driven) ------------------------------
#define VSLOTS       16                // token slots (grid-stride covers more)
#define VCOLS        64                // cols per chunk block
#define NCHUNK       (D_SZ / VCOLS)    // 80
#define KSPLIT       4
#define KSEG         (VIS_DIM / KSPLIT) // 192
#define VX_GRID      (VSLOTS * NCHUNK) // 1280

// Vision token list, filled by gather, consumed+reset by vx.
__device__ int g_cnt  = 0;
__device__ int g_done = 0;
__device__ int g_list[NTOK];

// ---------------------------------------------------------------------------
// K1: TMA bulk-copy gather of shared-vocab rows; appends vision token
// indices to g_list as a side effect (it reads every id anyway).
// ---------------------------------------------------------------------------
__global__ __launch_bounds__(THREADS)
void gather_tma_kernel(const int*   __restrict__ text,
                       const float* __restrict__ weight,
                       const float* __restrict__ fig,
                       float*       __restrict__ out)
{
    extern __shared__ __align__(128) char dsmem[];
    __shared__ int s_ids[TOK_PER_BLK];
    __shared__ int s_list[TOK_PER_BLK];

    const int t0 = blockIdx.x * TOK_PER_BLK;
    const int n  = min(TOK_PER_BLK, NTOK - t0);
    if (n <= 0) return;

    const int tid = threadIdx.x;
    for (int i = tid; i < n; i += THREADS) s_ids[i] = __ldg(&text[t0 + i]);
    __syncthreads();

    if (tid != 0) return;

    // compact shared-vocab tokens; publish vision tokens to the global list
    int m = 0;
    for (int i = 0; i < n; i++) {
        if (s_ids[i] < N_SHARED) {
            s_list[m++] = i;
        } else {
            int slot = atomicAdd(&g_cnt, 1);
            g_list[slot] = t0 + i;
        }
    }
    if (m == 0) return;

    uint32_t smem_base;
    asm("{ .reg .u64 t; cvta.to.shared.u64 t, %1; cvt.u32.u64 %0, t; }"
        : "=r"(smem_base) : "l"(dsmem));
    const uint32_t mbar0 = smem_base;
    const uint32_t buf0  = smem_base + 128;

    #pragma unroll
    for (int s = 0; s < NS; s++)
        asm volatile("mbarrier.init.shared.b64 [%0], 1;"
                     :: "r"(mbar0 + s * 8) : "memory");
    asm volatile("fence.proxy.async.shared::cta;" ::: "memory");

    auto src_of = [&](int j) -> const char* {
        int id = s_ids[s_list[j]];
        if (id < V_SZ) return (const char*)(weight + (size_t)id * D_SZ);
        return (const char*)(fig + (size_t)(id - V_SZ) * D_SZ);
    };

    auto issue_load = [&](int j) {
        uint32_t mb  = mbar0 + (j % NS) * 8;
        uint32_t dst = buf0 + (uint32_t)(j % NS) * ROW_BYTES;
        asm volatile("mbarrier.arrive.expect_tx.shared.b64 _, [%0], %1;"
                     :: "r"(mb), "r"((uint32_t)ROW_BYTES) : "memory");
        asm volatile("cp.async.bulk.shared::cta.global.mbarrier::complete_tx::bytes "
                     "[%0], [%1], %2, [%3];"
                     :: "r"(dst), "l"(src_of(j)), "r"((uint32_t)ROW_BYTES), "r"(mb)
                     : "memory");
    };

    const int npro = m < LOOKAHEAD ? m : LOOKAHEAD;
    for (int j = 0; j < npro; j++) issue_load(j);

    for (int j = 0; j < m; j++) {
        const uint32_t mb     = mbar0 + (j % NS) * 8;
        const uint32_t buf    = buf0 + (uint32_t)(j % NS) * ROW_BYTES;
        const uint32_t parity = (uint32_t)((j / NS) & 1);

        uint32_t done;
        asm volatile(
            "{\n\t.reg .pred p;\n\t"
            "mbarrier.try_wait.parity.acquire.cta.shared::cta.b64 p, [%1], %2;\n\t"
            "selp.b32 %0, 1, 0, p;\n\t}"
            : "=r"(done) : "r"(mb), "r"(parity) : "memory");
        if (!done) {
            asm volatile(
                "{\n\t.reg .pred P1;\n\t"
                "W_%=:\n\t"
                "mbarrier.try_wait.parity.acquire.cta.shared::cta.b64 P1, [%0], %1, 0x989680;\n\t"
                "@P1 bra.uni D_%=;\n\t"
                "bra.uni W_%=;\n\t"
                "D_%=:\n\t}"
                :: "r"(mb), "r"(parity) : "memory");
        }

        char* dst = (char*)(out + (size_t)(t0 + s_list[j]) * D_SZ);
        asm volatile("cp.async.bulk.global.shared::cta.bulk_group [%0], [%1], %2;"
                     :: "l"(dst), "r"(buf), "r"((uint32_t)ROW_BYTES) : "memory");
        asm volatile("cp.async.bulk.commit_group;" ::: "memory");

        if (j + LOOKAHEAD < m) {
            asm volatile("cp.async.bulk.wait_group.read 2;" ::: "memory");
            issue_load(j + LOOKAHEAD);
        }
    }
    asm volatile("cp.async.bulk.wait_group 0;" ::: "memory");
}

// ---------------------------------------------------------------------------
// K2: list-driven vision projection directly into out. No scanning.
// 1280 blocks = 16 token-slots x 80 col-chunks; grid-stride over slots.
// Active block: 64 cols x 4 k-segments, 32-wide load batches (6 DRAM rounds).
// Last block resets g_cnt/g_done for the next graph replay.
// ---------------------------------------------------------------------------
__global__ __launch_bounds__(THREADS)
void vx_kernel(const int*   __restrict__ text,
               const float* __restrict__ vis,     // [B*T, VIS_DIM]
               const float* __restrict__ fc_w,    // [VIS_DIM, D]
               const float* __restrict__ fc_b,    // [D]
               float*       __restrict__ out)     // [B*S, D]
{
    const int slot  = blockIdx.x / NCHUNK;
    const int chunk = blockIdx.x % NCHUNK;
    const int tid   = threadIdx.x;

    __shared__ float s_vis[VIS_DIM];
    __shared__ float s_part[KSPLIT][VCOLS];

    const int cnt = g_cnt;                    // list complete (prior kernel)

    const int kseg = tid >> 6;                // 0..3
    const int ci   = tid & 63;                // 0..63
    const int col  = chunk * VCOLS + ci;
    const int k0   = kseg * KSEG;

    for (int s = slot; s < cnt; s += VSLOTS) {
        const int tok = g_list[s];
        int id = __ldg(&text[tok]);
        int tv = id - N_SHARED;
        if (tv > T_SZ - 1) tv = T_SZ - 1;
        if (tv < 0)        tv = 0;
        int b = tok >> 11;                    // / S_SZ

        const float* vrow = vis + ((size_t)(b * T_SZ + tv)) * VIS_DIM;
        for (int i = tid; i < VIS_DIM; i += THREADS) s_vis[i] = vrow[i];
        __syncthreads();

        // 192 MACs: 6 batches of 32 loads in flight (warp -> 1 line per load)
        const float* w = fc_w + col;
        float acc = 0.f;
        #pragma unroll
        for (int kb = 0; kb < KSEG; kb += 32) {
            float wr[32];
            #pragma unroll
            for (int u = 0; u < 32; u++)
                wr[u] = __ldg(&w[(size_t)(k0 + kb + u) * D_SZ]);
            #pragma unroll
            for (int u = 0; u < 32; u++)
                acc = fmaf(s_vis[k0 + kb + u], wr[u], acc);
        }

        s_part[kseg][ci] = acc;
        __syncthreads();

        if (tid < VCOLS) {
            float r = __ldg(&fc_b[chunk * VCOLS + tid]);
            #pragma unroll
            for (int p = 0; p < KSPLIT; p++) r += s_part[p][tid];
            out[(size_t)tok * D_SZ + chunk * VCOLS + tid] = r;
        }
        __syncthreads();                      // before s_vis/s_part reuse
    }

    // ---- replay-safe reset: after ALL blocks have read g_cnt/g_list ----
    __syncthreads();                          // whole block done reading
    if (tid == 0) {
        int t = atomicAdd(&g_done, 1);
        if (t == (int)gridDim.x - 1) {        // every block has ticketed
            g_cnt  = 0;
            g_done = 0;
            __threadfence();
        }
    }
}

extern "C" void kernel_launch(void* const* d_in, const int* in_sizes, int n_in,
                              void* d_out, int out_size)
{
    const int*   text   = (const int*)  d_in[0];  // [B,S] int32
    const float* vis    = (const float*)d_in[1];  // [B,T,VIS_DIM]
    const float* weight = (const float*)d_in[2];  // [V,D]
    const float* fig    = (const float*)d_in[3];  // [2,D]
    const float* fc_w   = (const float*)d_in[4];  // [VIS_DIM,D]
    const float* fc_b   = (const float*)d_in[5];  // [D]
    float*       out    = (float*)d_out;

    cudaFuncSetAttribute(gather_tma_kernel,
                         cudaFuncAttributeMaxDynamicSharedMemorySize, SMEM_BYTES);
    gather_tma_kernel<<<GRID_GATHER, THREADS, SMEM_BYTES>>>(text, weight, fig, out);

    vx_kernel<<<VX_GRID, THREADS>>>(text, vis, fc_w, fc_b, out);
}